// round 1
// baseline (speedup 1.0000x reference)
#include <cuda_runtime.h>
#include <cuda_bf16.h>
#include <cstdint>

// Problem constants (match reference)
#define NN 100000
#define EE 3200000
#define DD 256

// ---------------- scratch (device globals; no allocations allowed) ------------
__device__ float g_buf_a[(size_t)NN * DD];
__device__ float g_buf_b[(size_t)NN * DD];
__device__ int   g_row_ptr[NN + 1];
__device__ int   g_cursor[NN + 1];   // doubles as counts
__device__ int   g_csr_col[EE];
__device__ float g_csr_w[EE];

// ---------------- CSR build ---------------------------------------------------
__global__ void zero_counts_kernel(int n) {
    int i = blockIdx.x * blockDim.x + threadIdx.x;
    if (i < n) g_cursor[i] = 0;
}

__global__ void hist_kernel(const int* __restrict__ er, int E) {
    int i = blockIdx.x * blockDim.x + threadIdx.x;
    if (i < E) atomicAdd(&g_cursor[er[i]], 1);
}

// single-block exclusive scan of counts -> row_ptr, and reset cursor = row_ptr
__global__ void scan_kernel(int n, int E) {
    const int T = 1024;
    int tid = threadIdx.x;
    int per = (n + T - 1) / T;
    int beg = tid * per;
    int end = beg + per; if (end > n) end = n;

    int sum = 0;
    for (int j = beg; j < end; j++) sum += g_cursor[j];

    __shared__ int s[T];
    s[tid] = sum;
    __syncthreads();
    for (int off = 1; off < T; off <<= 1) {
        int v = (tid >= off) ? s[tid - off] : 0;
        __syncthreads();
        s[tid] += v;
        __syncthreads();
    }
    int run = s[tid] - sum;  // exclusive offset for this thread's range
    for (int j = beg; j < end; j++) {
        int c = g_cursor[j];
        g_row_ptr[j] = run;
        g_cursor[j]  = run;   // scatter cursor
        run += c;
    }
    if (tid == 0) g_row_ptr[n] = s[T - 1];
}

__global__ void scatter_kernel(const int* __restrict__ er, const int* __restrict__ ec,
                               const float* __restrict__ ew, int E) {
    int i = blockIdx.x * blockDim.x + threadIdx.x;
    if (i < E) {
        int r = er[i];
        int p = atomicAdd(&g_cursor[r], 1);
        g_csr_col[p] = ec[i];
        g_csr_w[p]   = ew[i];
    }
}

// ---------------- GEMM: C = A(Mx256) @ B(256x256); also C2 = C ----------------
// 128x128 tile, K-step 8, 256 threads, 8x8 microtile per thread.
__global__ __launch_bounds__(256, 2)
void gemm_kernel(const float* __restrict__ A, const float* __restrict__ B,
                 float* __restrict__ C, float* __restrict__ C2, int M) {
    __shared__ __align__(16) float As[8][128];
    __shared__ __align__(16) float Bs[8][128];

    int tid = threadIdx.x;
    int tx = tid & 15;        // 0..15  (N direction)
    int ty = tid >> 4;        // 0..15  (M direction)
    int rowBase = blockIdx.y * 128;
    int colBase = blockIdx.x * 128;

    float acc[8][8];
#pragma unroll
    for (int i = 0; i < 8; i++)
#pragma unroll
        for (int j = 0; j < 8; j++) acc[i][j] = 0.f;

    int aRow  = tid >> 1;           // 0..127
    int aCol4 = (tid & 1) * 4;      // 0 or 4
    int bRow  = tid >> 5;           // 0..7
    int bCol4 = (tid & 31) * 4;     // 0..124

    for (int k0 = 0; k0 < 256; k0 += 8) {
        // load A tile (transposed into As[k][m])
        int gRow = rowBase + aRow;
        float4 av = make_float4(0.f, 0.f, 0.f, 0.f);
        if (gRow < M)
            av = *reinterpret_cast<const float4*>(&A[(size_t)gRow * 256 + k0 + aCol4]);
        As[aCol4 + 0][aRow] = av.x;
        As[aCol4 + 1][aRow] = av.y;
        As[aCol4 + 2][aRow] = av.z;
        As[aCol4 + 3][aRow] = av.w;
        // load B tile
        float4 bv = *reinterpret_cast<const float4*>(&B[(size_t)(k0 + bRow) * 256 + colBase + bCol4]);
        *reinterpret_cast<float4*>(&Bs[bRow][bCol4]) = bv;
        __syncthreads();

#pragma unroll
        for (int k = 0; k < 8; k++) {
            float4 a0 = *reinterpret_cast<const float4*>(&As[k][ty * 8]);
            float4 a1 = *reinterpret_cast<const float4*>(&As[k][ty * 8 + 4]);
            float4 b0 = *reinterpret_cast<const float4*>(&Bs[k][tx * 8]);
            float4 b1 = *reinterpret_cast<const float4*>(&Bs[k][tx * 8 + 4]);
            float a[8] = {a0.x, a0.y, a0.z, a0.w, a1.x, a1.y, a1.z, a1.w};
            float b[8] = {b0.x, b0.y, b0.z, b0.w, b1.x, b1.y, b1.z, b1.w};
#pragma unroll
            for (int i = 0; i < 8; i++)
#pragma unroll
                for (int j = 0; j < 8; j++) acc[i][j] = fmaf(a[i], b[j], acc[i][j]);
        }
        __syncthreads();
    }

#pragma unroll
    for (int i = 0; i < 8; i++) {
        int r = rowBase + ty * 8 + i;
        if (r < M) {
            int c = colBase + tx * 8;
            float4 v0 = make_float4(acc[i][0], acc[i][1], acc[i][2], acc[i][3]);
            float4 v1 = make_float4(acc[i][4], acc[i][5], acc[i][6], acc[i][7]);
            size_t o = (size_t)r * 256 + c;
            *reinterpret_cast<float4*>(&C[o])      = v0;
            *reinterpret_cast<float4*>(&C[o + 4])  = v1;
            *reinterpret_cast<float4*>(&C2[o])     = v0;
            *reinterpret_cast<float4*>(&C2[o + 4]) = v1;
        }
    }
}

// ---------------- SpMM: out[row] = sum_e w_e * in[col_e]; accum += out --------
// one block (256 threads) per row; thread d owns feature d.
__global__ __launch_bounds__(256)
void spmm_kernel(const float* __restrict__ in, float* __restrict__ outbuf,
                 float* __restrict__ accum, const float* __restrict__ bias) {
    int row = blockIdx.x;
    int d = threadIdx.x;
    int beg = __ldg(&g_row_ptr[row]);
    int end = __ldg(&g_row_ptr[row + 1]);

    __shared__ int   scol[128];
    __shared__ float sw[128];

    float acc = 0.f;
    for (int base = beg; base < end; base += 128) {
        int m = end - base; if (m > 128) m = 128;
        __syncthreads();
        if (d < m) {
            scol[d] = g_csr_col[base + d];
            sw[d]   = g_csr_w[base + d];
        }
        __syncthreads();
        int j = 0;
        for (; j + 4 <= m; j += 4) {
            int c0 = scol[j]     * 256 + d;
            int c1 = scol[j + 1] * 256 + d;
            int c2 = scol[j + 2] * 256 + d;
            int c3 = scol[j + 3] * 256 + d;
            float w0 = sw[j], w1 = sw[j + 1], w2 = sw[j + 2], w3 = sw[j + 3];
            float v0 = __ldg(in + c0);
            float v1 = __ldg(in + c1);
            float v2 = __ldg(in + c2);
            float v3 = __ldg(in + c3);
            acc = fmaf(w0, v0, acc);
            acc = fmaf(w1, v1, acc);
            acc = fmaf(w2, v2, acc);
            acc = fmaf(w3, v3, acc);
        }
        for (; j < m; j++)
            acc = fmaf(sw[j], __ldg(in + scol[j] * 256 + d), acc);
    }

    int o = row * 256 + d;
    outbuf[o] = acc;
    float a = accum[o] + acc;
    if (bias) a += __ldg(bias + d);
    accum[o] = a;
}

// ---------------- launch ------------------------------------------------------
extern "C" void kernel_launch(void* const* d_in, const int* in_sizes, int n_in,
                              void* d_out, int out_size) {
    const float* x    = (const float*)d_in[0];
    const float* w    = (const float*)d_in[1];
    const float* bias = (const float*)d_in[2];
    const float* ew   = (const float*)d_in[3];
    const int*   er   = (const int*)d_in[4];
    const int*   ec   = (const int*)d_in[5];
    float* out = (float*)d_out;

    const int N = in_sizes[0] / DD;   // 100000
    const int E = in_sizes[3];        // 3200000

    void *pa = nullptr, *pb = nullptr;
    cudaGetSymbolAddress(&pa, g_buf_a);
    cudaGetSymbolAddress(&pb, g_buf_b);
    float* bufA = (float*)pa;
    float* bufB = (float*)pb;

    // 1) CSR build
    zero_counts_kernel<<<(N + 256) / 256, 256>>>(N + 1);
    hist_kernel<<<(E + 255) / 256, 256>>>(er, E);
    scan_kernel<<<1, 1024>>>(N, E);
    scatter_kernel<<<(E + 255) / 256, 256>>>(er, ec, ew, E);

    // 2) support = x @ W  -> bufA, and initialize accumulator d_out = support
    dim3 ggrid(2, (N + 127) / 128);
    gemm_kernel<<<ggrid, 256>>>(x, w, bufA, out, N);

    // 3) three SpMM hops, accumulating into d_out; bias fused into last hop
    spmm_kernel<<<N, 256>>>(bufA, bufB, out, nullptr);
    spmm_kernel<<<N, 256>>>(bufB, bufA, out, nullptr);
    spmm_kernel<<<N, 256>>>(bufA, bufB, out, bias);
}

// round 2
// speedup vs baseline: 1.5702x; 1.5702x over previous
#include <cuda_runtime.h>
#include <cuda_fp16.h>
#include <cstdint>

// Problem constants (match reference)
#define NN 100000
#define EE 3200000
#define DD 256

// ---------------- scratch (device globals; no allocations allowed) ------------
__device__ __half2 g_hbuf_a[(size_t)NN * (DD / 2)];   // 51.2 MB
__device__ __half2 g_hbuf_b[(size_t)NN * (DD / 2)];   // 51.2 MB
__device__ int     g_row_ptr[NN + 1];
__device__ int     g_cursor[NN + 1];                  // doubles as counts
__device__ int2    g_csr[EE];                         // {col, weight-bits} interleaved

// ---------------- CSR build ---------------------------------------------------
__global__ void zero_counts_kernel(int n) {
    int i = blockIdx.x * blockDim.x + threadIdx.x;
    if (i < n) g_cursor[i] = 0;
}

__global__ void hist_kernel(const int* __restrict__ er, int E) {
    int i = blockIdx.x * blockDim.x + threadIdx.x;
    if (i < E) atomicAdd(&g_cursor[er[i]], 1);
}

// single-block exclusive scan of counts -> row_ptr, and reset cursor = row_ptr
__global__ void scan_kernel(int n, int E) {
    const int T = 1024;
    int tid = threadIdx.x;
    int per = (n + T - 1) / T;
    int beg = tid * per;
    int end = beg + per; if (end > n) end = n;

    int sum = 0;
    for (int j = beg; j < end; j++) sum += g_cursor[j];

    __shared__ int s[T];
    s[tid] = sum;
    __syncthreads();
    for (int off = 1; off < T; off <<= 1) {
        int v = (tid >= off) ? s[tid - off] : 0;
        __syncthreads();
        s[tid] += v;
        __syncthreads();
    }
    int run = s[tid] - sum;  // exclusive offset for this thread's range
    for (int j = beg; j < end; j++) {
        int c = g_cursor[j];
        g_row_ptr[j] = run;
        g_cursor[j]  = run;   // scatter cursor
        run += c;
    }
    if (tid == 0) g_row_ptr[n] = s[T - 1];
}

__global__ void scatter_kernel(const int* __restrict__ er, const int* __restrict__ ec,
                               const float* __restrict__ ew, int E) {
    int i = blockIdx.x * blockDim.x + threadIdx.x;
    if (i < E) {
        int r = er[i];
        int p = atomicAdd(&g_cursor[r], 1);
        g_csr[p] = make_int2(ec[i], __float_as_int(ew[i]));
    }
}

// ---------------- GEMM: C = A(Mx256) @ B(256x256) -----------------------------
// 128x128 tile, K-step 8, 256 threads, 8x8 microtile per thread.
// Epilogue writes fp32 (accumulator init) AND packed fp16 (gather buffer).
__global__ __launch_bounds__(256, 2)
void gemm_kernel(const float* __restrict__ A, const float* __restrict__ B,
                 float* __restrict__ C, __half2* __restrict__ Ch, int M) {
    __shared__ __align__(16) float As[8][128];
    __shared__ __align__(16) float Bs[8][128];

    int tid = threadIdx.x;
    int tx = tid & 15;        // 0..15  (N direction)
    int ty = tid >> 4;        // 0..15  (M direction)
    int rowBase = blockIdx.y * 128;
    int colBase = blockIdx.x * 128;

    float acc[8][8];
#pragma unroll
    for (int i = 0; i < 8; i++)
#pragma unroll
        for (int j = 0; j < 8; j++) acc[i][j] = 0.f;

    int aRow  = tid >> 1;           // 0..127
    int aCol4 = (tid & 1) * 4;      // 0 or 4
    int bRow  = tid >> 5;           // 0..7
    int bCol4 = (tid & 31) * 4;     // 0..124

    for (int k0 = 0; k0 < 256; k0 += 8) {
        int gRow = rowBase + aRow;
        float4 av = make_float4(0.f, 0.f, 0.f, 0.f);
        if (gRow < M)
            av = *reinterpret_cast<const float4*>(&A[(size_t)gRow * 256 + k0 + aCol4]);
        As[aCol4 + 0][aRow] = av.x;
        As[aCol4 + 1][aRow] = av.y;
        As[aCol4 + 2][aRow] = av.z;
        As[aCol4 + 3][aRow] = av.w;
        float4 bv = *reinterpret_cast<const float4*>(&B[(size_t)(k0 + bRow) * 256 + colBase + bCol4]);
        *reinterpret_cast<float4*>(&Bs[bRow][bCol4]) = bv;
        __syncthreads();

#pragma unroll
        for (int k = 0; k < 8; k++) {
            float4 a0 = *reinterpret_cast<const float4*>(&As[k][ty * 8]);
            float4 a1 = *reinterpret_cast<const float4*>(&As[k][ty * 8 + 4]);
            float4 b0 = *reinterpret_cast<const float4*>(&Bs[k][tx * 8]);
            float4 b1 = *reinterpret_cast<const float4*>(&Bs[k][tx * 8 + 4]);
            float a[8] = {a0.x, a0.y, a0.z, a0.w, a1.x, a1.y, a1.z, a1.w};
            float b[8] = {b0.x, b0.y, b0.z, b0.w, b1.x, b1.y, b1.z, b1.w};
#pragma unroll
            for (int i = 0; i < 8; i++)
#pragma unroll
                for (int j = 0; j < 8; j++) acc[i][j] = fmaf(a[i], b[j], acc[i][j]);
        }
        __syncthreads();
    }

#pragma unroll
    for (int i = 0; i < 8; i++) {
        int r = rowBase + ty * 8 + i;
        if (r < M) {
            int c = colBase + tx * 8;
            float4 v0 = make_float4(acc[i][0], acc[i][1], acc[i][2], acc[i][3]);
            float4 v1 = make_float4(acc[i][4], acc[i][5], acc[i][6], acc[i][7]);
            size_t o = (size_t)r * 256 + c;
            *reinterpret_cast<float4*>(&C[o])     = v0;
            *reinterpret_cast<float4*>(&C[o + 4]) = v1;
            // packed fp16 copy for the SpMM gather buffer
            __half2 h0 = __floats2half2_rn(acc[i][0], acc[i][1]);
            __half2 h1 = __floats2half2_rn(acc[i][2], acc[i][3]);
            __half2 h2 = __floats2half2_rn(acc[i][4], acc[i][5]);
            __half2 h3 = __floats2half2_rn(acc[i][6], acc[i][7]);
            uint4 hv;
            hv.x = *reinterpret_cast<uint32_t*>(&h0);
            hv.y = *reinterpret_cast<uint32_t*>(&h1);
            hv.z = *reinterpret_cast<uint32_t*>(&h2);
            hv.w = *reinterpret_cast<uint32_t*>(&h3);
            *reinterpret_cast<uint4*>(&Ch[(size_t)r * 128 + (c >> 1)]) = hv;
        }
    }
}

// ---------------- SpMM: out[row] = sum_e w_e * in[col_e] ----------------------
// one block (128 threads) per row; thread d owns feature pair (2d, 2d+1).
// Writes fp16 hop buffer and accumulates fp32 into `accum` (+bias on last hop).
__global__ __launch_bounds__(128)
void spmm_kernel(const __half2* __restrict__ in, __half2* __restrict__ outbuf,
                 float* __restrict__ accum, const float* __restrict__ bias) {
    int row = blockIdx.x;
    int d = threadIdx.x;                     // 0..127
    int beg = __ldg(&g_row_ptr[row]);
    int end = __ldg(&g_row_ptr[row + 1]);

    __shared__ int2 se[128];

    float accx = 0.f, accy = 0.f;
    for (int base = beg; base < end; base += 128) {
        int m = end - base; if (m > 128) m = 128;
        __syncthreads();
        if (d < m) se[d] = __ldg(&g_csr[base + d]);
        __syncthreads();
        int j = 0;
        for (; j + 4 <= m; j += 4) {
            int2 e0 = se[j], e1 = se[j + 1], e2 = se[j + 2], e3 = se[j + 3];
            __half2 v0 = __ldg(in + (size_t)e0.x * 128 + d);
            __half2 v1 = __ldg(in + (size_t)e1.x * 128 + d);
            __half2 v2 = __ldg(in + (size_t)e2.x * 128 + d);
            __half2 v3 = __ldg(in + (size_t)e3.x * 128 + d);
            float w0 = __int_as_float(e0.y), w1 = __int_as_float(e1.y);
            float w2 = __int_as_float(e2.y), w3 = __int_as_float(e3.y);
            float2 f0 = __half22float2(v0);
            float2 f1 = __half22float2(v1);
            float2 f2 = __half22float2(v2);
            float2 f3 = __half22float2(v3);
            accx = fmaf(w0, f0.x, accx); accy = fmaf(w0, f0.y, accy);
            accx = fmaf(w1, f1.x, accx); accy = fmaf(w1, f1.y, accy);
            accx = fmaf(w2, f2.x, accx); accy = fmaf(w2, f2.y, accy);
            accx = fmaf(w3, f3.x, accx); accy = fmaf(w3, f3.y, accy);
        }
        for (; j < m; j++) {
            int2 e = se[j];
            float2 f = __half22float2(__ldg(in + (size_t)e.x * 128 + d));
            float w = __int_as_float(e.y);
            accx = fmaf(w, f.x, accx);
            accy = fmaf(w, f.y, accy);
        }
    }

    size_t o = (size_t)row * 128 + d;
    outbuf[o] = __floats2half2_rn(accx, accy);

    float2* acc2 = reinterpret_cast<float2*>(accum);
    float2 a = acc2[o];
    a.x += accx; a.y += accy;
    if (bias) {
        a.x += __ldg(bias + 2 * d);
        a.y += __ldg(bias + 2 * d + 1);
    }
    acc2[o] = a;
}

// ---------------- launch ------------------------------------------------------
extern "C" void kernel_launch(void* const* d_in, const int* in_sizes, int n_in,
                              void* d_out, int out_size) {
    const float* x    = (const float*)d_in[0];
    const float* w    = (const float*)d_in[1];
    const float* bias = (const float*)d_in[2];
    const float* ew   = (const float*)d_in[3];
    const int*   er   = (const int*)d_in[4];
    const int*   ec   = (const int*)d_in[5];
    float* out = (float*)d_out;

    const int N = in_sizes[0] / DD;   // 100000
    const int E = in_sizes[3];        // 3200000

    void *pa = nullptr, *pb = nullptr;
    cudaGetSymbolAddress(&pa, g_hbuf_a);
    cudaGetSymbolAddress(&pb, g_hbuf_b);
    __half2* hA = (__half2*)pa;
    __half2* hB = (__half2*)pb;

    // 1) CSR build
    zero_counts_kernel<<<(N + 256) / 256, 256>>>(N + 1);
    hist_kernel<<<(E + 255) / 256, 256>>>(er, E);
    scan_kernel<<<1, 1024>>>(N, E);
    scatter_kernel<<<(E + 255) / 256, 256>>>(er, ec, ew, E);

    // 2) support = x @ W  -> out (fp32 accumulator init) and hA (fp16 gather buf)
    dim3 ggrid(2, (N + 127) / 128);
    gemm_kernel<<<ggrid, 256>>>(x, w, out, hA, N);

    // 3) three SpMM hops, accumulating into d_out; bias fused into last hop
    spmm_kernel<<<N, 128>>>(hA, hB, out, nullptr);
    spmm_kernel<<<N, 128>>>(hB, hA, out, nullptr);
    spmm_kernel<<<N, 128>>>(hA, hB, out, bias);
}

// round 7
// speedup vs baseline: 1.8343x; 1.1682x over previous
#include <cuda_runtime.h>
#include <cuda_fp16.h>
#include <cstdint>

// Problem constants (match reference)
#define NN 100000
#define EE 3200000
#define DD 256

// ---------------- scratch (device globals; no allocations allowed) ------------
__device__ __half2 g_hbuf_a[(size_t)NN * 128];   // support (fp16)     51.2 MB
__device__ __half2 g_hbuf_b[(size_t)NN * 128];   // hop1               51.2 MB
__device__ __half2 g_hbuf_c[(size_t)NN * 128];   // hop2               51.2 MB
__device__ __half2 g_hbuf_d[(size_t)NN * 128];   // hop3               51.2 MB
__device__ __half2 g_Ah[(size_t)NN * 128];       // x hi split         51.2 MB
__device__ __half2 g_Al[(size_t)NN * 128];       // x lo split         51.2 MB
__device__ __half2 g_Bh2[256 * 128];             // W^T hi  [N,K]
__device__ __half2 g_Bl2[256 * 128];             // W^T lo  [N,K]
__device__ int     g_row_ptr[NN + 1];
__device__ int     g_cursor[NN + 1];             // doubles as counts
__device__ int2    g_csr[EE];                    // {col, weight-bits} interleaved

// ---------------- CSR build ---------------------------------------------------
__global__ void zero_counts_kernel(int n) {
    int i = blockIdx.x * blockDim.x + threadIdx.x;
    if (i < n) g_cursor[i] = 0;
}

__global__ void hist_kernel(const int* __restrict__ er, int E) {
    int i = blockIdx.x * blockDim.x + threadIdx.x;
    if (i < E) atomicAdd(&g_cursor[er[i]], 1);
}

__global__ void scan_kernel(int n, int E) {
    const int T = 1024;
    int tid = threadIdx.x;
    int per = (n + T - 1) / T;
    int beg = tid * per;
    int end = beg + per; if (end > n) end = n;

    int sum = 0;
    for (int j = beg; j < end; j++) sum += g_cursor[j];

    __shared__ int s[T];
    s[tid] = sum;
    __syncthreads();
    for (int off = 1; off < T; off <<= 1) {
        int v = (tid >= off) ? s[tid - off] : 0;
        __syncthreads();
        s[tid] += v;
        __syncthreads();
    }
    int run = s[tid] - sum;
    for (int j = beg; j < end; j++) {
        int c = g_cursor[j];
        g_row_ptr[j] = run;
        g_cursor[j]  = run;
        run += c;
    }
    if (tid == 0) g_row_ptr[n] = s[T - 1];
}

__global__ void scatter_kernel(const int* __restrict__ er, const int* __restrict__ ec,
                               const float* __restrict__ ew, int E) {
    int i = blockIdx.x * blockDim.x + threadIdx.x;
    if (i < E) {
        int r = er[i];
        int p = atomicAdd(&g_cursor[r], 1);
        g_csr[p] = make_int2(ec[i], __float_as_int(ew[i]));
    }
}

// ---------------- operand prep -------------------------------------------------
// split x (fp32) into hi/lo fp16
__global__ void asplit_kernel(const float* __restrict__ x, int total2) {
    int i = blockIdx.x * blockDim.x + threadIdx.x;
    if (i < total2) {
        float2 v = reinterpret_cast<const float2*>(x)[i];
        __half hx = __float2half_rn(v.x), hy = __float2half_rn(v.y);
        g_Ah[i] = __halves2half2(hx, hy);
        g_Al[i] = __halves2half2(__float2half_rn(v.x - __half2float(hx)),
                                 __float2half_rn(v.y - __half2float(hy)));
    }
}

// W fp32 [K,N] -> W^T hi/lo fp16 [N,K] row-major
__global__ void bprep2_kernel(const float* __restrict__ W) {
    int idx = blockIdx.x * blockDim.x + threadIdx.x;   // 0..32767
    int n  = idx >> 7;
    int k2 = (idx & 127) * 2;
    float w0 = __ldg(&W[(size_t)k2 * 256 + n]);
    float w1 = __ldg(&W[(size_t)(k2 + 1) * 256 + n]);
    __half h0 = __float2half_rn(w0), h1 = __float2half_rn(w1);
    g_Bh2[n * 128 + (k2 >> 1)] = __halves2half2(h0, h1);
    g_Bl2[n * 128 + (k2 >> 1)] =
        __halves2half2(__float2half_rn(w0 - __half2float(h0)),
                       __float2half_rn(w1 - __half2float(h1)));
}

// ---------------- mma.sync GEMM: C = A(Mx256) @ W(256x256) --------------------
// split-fp16 hi/lo, 3 terms, fp32 accum. CTA 128x128, 4 warps of 64x64.
__device__ __forceinline__ void mma16816(float* c, const uint32_t* a,
                                         uint32_t b0, uint32_t b1) {
    asm volatile(
        "mma.sync.aligned.m16n8k16.row.col.f32.f16.f16.f32 "
        "{%0,%1,%2,%3}, {%4,%5,%6,%7}, {%8,%9}, {%0,%1,%2,%3};"
        : "+f"(c[0]), "+f"(c[1]), "+f"(c[2]), "+f"(c[3])
        : "r"(a[0]), "r"(a[1]), "r"(a[2]), "r"(a[3]), "r"(b0), "r"(b1));
}

#define SMEM_PITCH 20   // halves per row (40 bytes): conflict-free

__global__ __launch_bounds__(128, 2)
void gemm_mma_kernel(const __half* __restrict__ Ah, const __half* __restrict__ Al,
                     const __half* __restrict__ Bh, const __half* __restrict__ Bl,
                     float* __restrict__ C, __half2* __restrict__ Ch, int M) {
    __shared__ __half sAh[128 * SMEM_PITCH];
    __shared__ __half sAl[128 * SMEM_PITCH];
    __shared__ __half sBh[128 * SMEM_PITCH];
    __shared__ __half sBl[128 * SMEM_PITCH];

    int tid  = threadIdx.x;
    int lane = tid & 31;
    int warp = tid >> 5;
    int g    = lane >> 2;
    int tig  = lane & 3;
    int warpM = (warp >> 1) * 64;
    int warpN = (warp & 1) * 64;
    int rowBase = blockIdx.y * 128;
    int colBase = blockIdx.x * 128;

    float acc[4][8][4];
#pragma unroll
    for (int i = 0; i < 4; i++)
#pragma unroll
        for (int j = 0; j < 8; j++)
#pragma unroll
            for (int q = 0; q < 4; q++) acc[i][j][q] = 0.f;

    // per-thread staging: row `tid` of A (hi/lo) and row `tid` of B (hi/lo), 16 halves each
    int aRow = rowBase + tid;
    bool aOk = (aRow < M);
    const uint4* gAh = reinterpret_cast<const uint4*>(Ah + (size_t)aRow * 256);
    const uint4* gAl = reinterpret_cast<const uint4*>(Al + (size_t)aRow * 256);
    const uint4* gBh = reinterpret_cast<const uint4*>(Bh + (size_t)(colBase + tid) * 256);
    const uint4* gBl = reinterpret_cast<const uint4*>(Bl + (size_t)(colBase + tid) * 256);

    uint4 rh0, rh1, rl0, rl1, sh0, sh1, sl0, sl1;
    const uint4 Z = make_uint4(0, 0, 0, 0);

    // prefetch stage 0 (ks halves offset = ks*16 -> uint4 index = ks*2)
    rh0 = aOk ? __ldg(&gAh[0]) : Z;  rh1 = aOk ? __ldg(&gAh[1]) : Z;
    rl0 = aOk ? __ldg(&gAl[0]) : Z;  rl1 = aOk ? __ldg(&gAl[1]) : Z;
    sh0 = __ldg(&gBh[0]);            sh1 = __ldg(&gBh[1]);
    sl0 = __ldg(&gBl[0]);            sl1 = __ldg(&gBl[1]);

    for (int ks = 0; ks < 16; ks++) {
        __syncthreads();
        // store staged tile
        {
            uint2* dA = reinterpret_cast<uint2*>(&sAh[tid * SMEM_PITCH]);
            dA[0] = make_uint2(rh0.x, rh0.y); dA[1] = make_uint2(rh0.z, rh0.w);
            dA[2] = make_uint2(rh1.x, rh1.y); dA[3] = make_uint2(rh1.z, rh1.w);
            uint2* dAl = reinterpret_cast<uint2*>(&sAl[tid * SMEM_PITCH]);
            dAl[0] = make_uint2(rl0.x, rl0.y); dAl[1] = make_uint2(rl0.z, rl0.w);
            dAl[2] = make_uint2(rl1.x, rl1.y); dAl[3] = make_uint2(rl1.z, rl1.w);
            uint2* dB = reinterpret_cast<uint2*>(&sBh[tid * SMEM_PITCH]);
            dB[0] = make_uint2(sh0.x, sh0.y); dB[1] = make_uint2(sh0.z, sh0.w);
            dB[2] = make_uint2(sh1.x, sh1.y); dB[3] = make_uint2(sh1.z, sh1.w);
            uint2* dBl = reinterpret_cast<uint2*>(&sBl[tid * SMEM_PITCH]);
            dBl[0] = make_uint2(sl0.x, sl0.y); dBl[1] = make_uint2(sl0.z, sl0.w);
            dBl[2] = make_uint2(sl1.x, sl1.y); dBl[3] = make_uint2(sl1.z, sl1.w);
        }
        __syncthreads();
        // prefetch next stage
        if (ks < 15) {
            int o = (ks + 1) * 2;
            rh0 = aOk ? __ldg(&gAh[o]) : Z;  rh1 = aOk ? __ldg(&gAh[o + 1]) : Z;
            rl0 = aOk ? __ldg(&gAl[o]) : Z;  rl1 = aOk ? __ldg(&gAl[o + 1]) : Z;
            sh0 = __ldg(&gBh[o]);            sh1 = __ldg(&gBh[o + 1]);
            sl0 = __ldg(&gBl[o]);            sl1 = __ldg(&gBl[o + 1]);
        }

        // load A fragments for 4 m-tiles (hi and lo)
        uint32_t ah[4][4], al[4][4];
#pragma unroll
        for (int mi = 0; mi < 4; mi++) {
            int r = warpM + mi * 16 + g;
            ah[mi][0] = *reinterpret_cast<const uint32_t*>(&sAh[r * SMEM_PITCH + 2 * tig]);
            ah[mi][1] = *reinterpret_cast<const uint32_t*>(&sAh[(r + 8) * SMEM_PITCH + 2 * tig]);
            ah[mi][2] = *reinterpret_cast<const uint32_t*>(&sAh[r * SMEM_PITCH + 2 * tig + 8]);
            ah[mi][3] = *reinterpret_cast<const uint32_t*>(&sAh[(r + 8) * SMEM_PITCH + 2 * tig + 8]);
            al[mi][0] = *reinterpret_cast<const uint32_t*>(&sAl[r * SMEM_PITCH + 2 * tig]);
            al[mi][1] = *reinterpret_cast<const uint32_t*>(&sAl[(r + 8) * SMEM_PITCH + 2 * tig]);
            al[mi][2] = *reinterpret_cast<const uint32_t*>(&sAl[r * SMEM_PITCH + 2 * tig + 8]);
            al[mi][3] = *reinterpret_cast<const uint32_t*>(&sAl[(r + 8) * SMEM_PITCH + 2 * tig + 8]);
        }
#pragma unroll
        for (int ni = 0; ni < 8; ni++) {
            int n = warpN + ni * 8 + g;
            uint32_t bh0 = *reinterpret_cast<const uint32_t*>(&sBh[n * SMEM_PITCH + 2 * tig]);
            uint32_t bh1 = *reinterpret_cast<const uint32_t*>(&sBh[n * SMEM_PITCH + 2 * tig + 8]);
            uint32_t bl0 = *reinterpret_cast<const uint32_t*>(&sBl[n * SMEM_PITCH + 2 * tig]);
            uint32_t bl1 = *reinterpret_cast<const uint32_t*>(&sBl[n * SMEM_PITCH + 2 * tig + 8]);
#pragma unroll
            for (int mi = 0; mi < 4; mi++) {
                mma16816(acc[mi][ni], ah[mi], bh0, bh1);   // hi*hi
                mma16816(acc[mi][ni], al[mi], bh0, bh1);   // lo*hi
                mma16816(acc[mi][ni], ah[mi], bl0, bl1);   // hi*lo
            }
        }
    }

    // epilogue: fp32 (support init in d_out) + packed fp16 (gather buffer)
#pragma unroll
    for (int mi = 0; mi < 4; mi++) {
#pragma unroll
        for (int ni = 0; ni < 8; ni++) {
            int row0 = rowBase + warpM + mi * 16 + g;
            int col  = colBase + warpN + ni * 8 + 2 * tig;
            float* a = acc[mi][ni];
            if (row0 < M) {
                *reinterpret_cast<float2*>(&C[(size_t)row0 * 256 + col]) = make_float2(a[0], a[1]);
                Ch[(size_t)row0 * 128 + (col >> 1)] = __floats2half2_rn(a[0], a[1]);
            }
            int row1 = row0 + 8;
            if (row1 < M) {
                *reinterpret_cast<float2*>(&C[(size_t)row1 * 256 + col]) = make_float2(a[2], a[3]);
                Ch[(size_t)row1 * 128 + (col >> 1)] = __floats2half2_rn(a[2], a[3]);
            }
        }
    }
}

// ---------------- SpMM: out[row] = sum_e w_e * in[col_e] (fp16 out only) ------
__global__ __launch_bounds__(128)
void spmm_kernel(const __half2* __restrict__ in, __half2* __restrict__ outbuf) {
    int row = blockIdx.x;
    int d = threadIdx.x;                     // 0..127
    int beg = __ldg(&g_row_ptr[row]);
    int end = __ldg(&g_row_ptr[row + 1]);

    __shared__ int2 se[128];

    float accx = 0.f, accy = 0.f;
    for (int base = beg; base < end; base += 128) {
        int m = end - base; if (m > 128) m = 128;
        __syncthreads();
        if (d < m) se[d] = __ldg(&g_csr[base + d]);
        __syncthreads();
        int j = 0;
        for (; j + 4 <= m; j += 4) {
            int2 e0 = se[j], e1 = se[j + 1], e2 = se[j + 2], e3 = se[j + 3];
            __half2 v0 = __ldg(in + (size_t)e0.x * 128 + d);
            __half2 v1 = __ldg(in + (size_t)e1.x * 128 + d);
            __half2 v2 = __ldg(in + (size_t)e2.x * 128 + d);
            __half2 v3 = __ldg(in + (size_t)e3.x * 128 + d);
            float w0 = __int_as_float(e0.y), w1 = __int_as_float(e1.y);
            float w2 = __int_as_float(e2.y), w3 = __int_as_float(e3.y);
            float2 f0 = __half22float2(v0);
            float2 f1 = __half22float2(v1);
            float2 f2 = __half22float2(v2);
            float2 f3 = __half22float2(v3);
            accx = fmaf(w0, f0.x, accx); accy = fmaf(w0, f0.y, accy);
            accx = fmaf(w1, f1.x, accx); accy = fmaf(w1, f1.y, accy);
            accx = fmaf(w2, f2.x, accx); accy = fmaf(w2, f2.y, accy);
            accx = fmaf(w3, f3.x, accx); accy = fmaf(w3, f3.y, accy);
        }
        for (; j < m; j++) {
            int2 e = se[j];
            float2 f = __half22float2(__ldg(in + (size_t)e.x * 128 + d));
            float w = __int_as_float(e.y);
            accx = fmaf(w, f.x, accx);
            accy = fmaf(w, f.y, accy);
        }
    }

    outbuf[(size_t)row * 128 + d] = __floats2half2_rn(accx, accy);
}

// ---------------- final: out += h1 + h2 + h3 + bias ---------------------------
__global__ __launch_bounds__(128)
void final_add_kernel(float* __restrict__ out, const float* __restrict__ bias) {
    int row = blockIdx.x;
    int d = threadIdx.x;
    size_t o = (size_t)row * 128 + d;
    float2 a = reinterpret_cast<float2*>(out)[o];
    float2 f1 = __half22float2(g_hbuf_b[o]);
    float2 f2 = __half22float2(g_hbuf_c[o]);
    float2 f3 = __half22float2(g_hbuf_d[o]);
    a.x += f1.x + f2.x + f3.x + __ldg(bias + 2 * d);
    a.y += f1.y + f2.y + f3.y + __ldg(bias + 2 * d + 1);
    reinterpret_cast<float2*>(out)[o] = a;
}

// ---------------- launch ------------------------------------------------------
extern "C" void kernel_launch(void* const* d_in, const int* in_sizes, int n_in,
                              void* d_out, int out_size) {
    const float* x    = (const float*)d_in[0];
    const float* w    = (const float*)d_in[1];
    const float* bias = (const float*)d_in[2];
    const float* ew   = (const float*)d_in[3];
    const int*   er   = (const int*)d_in[4];
    const int*   ec   = (const int*)d_in[5];
    float* out = (float*)d_out;

    const int N = in_sizes[0] / DD;   // 100000
    const int E = in_sizes[3];        // 3200000

    void *pa, *pb, *pc, *pd, *pah, *pal, *pbh, *pbl;
    cudaGetSymbolAddress(&pa,  g_hbuf_a);
    cudaGetSymbolAddress(&pb,  g_hbuf_b);
    cudaGetSymbolAddress(&pc,  g_hbuf_c);
    cudaGetSymbolAddress(&pd,  g_hbuf_d);
    cudaGetSymbolAddress(&pah, g_Ah);
    cudaGetSymbolAddress(&pal, g_Al);
    cudaGetSymbolAddress(&pbh, g_Bh2);
    cudaGetSymbolAddress(&pbl, g_Bl2);
    __half2* hA = (__half2*)pa;
    __half2* hB = (__half2*)pb;
    __half2* hC = (__half2*)pc;
    __half2* hD = (__half2*)pd;

    // 1) CSR build + operand prep
    zero_counts_kernel<<<(N + 256) / 256, 256>>>(N + 1);
    hist_kernel<<<(E + 255) / 256, 256>>>(er, E);
    scan_kernel<<<1, 1024>>>(N, E);
    scatter_kernel<<<(E + 255) / 256, 256>>>(er, ec, ew, E);
    asplit_kernel<<<(N * 128 + 255) / 256, 256>>>(x, N * 128);
    bprep2_kernel<<<128, 256>>>(w);

    // 2) support = x @ W  -> d_out (fp32) and hA (fp16 gather buf)
    dim3 ggrid(2, (N + 127) / 128);
    gemm_mma_kernel<<<ggrid, 128>>>((const __half*)pah, (const __half*)pal,
                                    (const __half*)pbh, (const __half*)pbl,
                                    out, hA, N);

    // 3) three SpMM hops (fp16 buffers only)
    spmm_kernel<<<N, 128>>>(hA, hB);
    spmm_kernel<<<N, 128>>>(hB, hC);
    spmm_kernel<<<N, 128>>>(hC, hD);

    // 4) out += h1 + h2 + h3 + bias
    final_add_kernel<<<N, 128>>>(out, bias);
}